// round 6
// baseline (speedup 1.0000x reference)
#include <cuda_runtime.h>
#include <math.h>

// Problem constants (fixed by the reference)
#define NN  50000
#define EE  800000
#define F3  32
#define KK  16
#define NB  ((NN + 255) / 256)     // 196 scan blocks

// ---------------- scratch (__device__ globals; no allocs allowed) ----------
// Per-graph duplicated so both graphs' pipelines interleave freely.
__device__ float g_P[2][NN * 64];    // activations ping
__device__ float g_Q[2][NN * 64];    // activations pong
__device__ int2  g_csr[2][EE];       // CSR edge record: {src, __float_as_int(w)}
__device__ int   g_rowptr[2][NN];
__device__ int   g_deg[2][NN];       // edge in-degree (self-loop NOT counted)
__device__ int   g_cur[2][NN];
__device__ int   g_scanTmp[2][NN];
__device__ int   g_bsum[2][256];
__device__ int   g_boff[2][256];
__device__ float g_dinv[2][NN];
__device__ float g_m[2][F3];
__device__ float g_ctx[2][F3];
__device__ float g_pool[2][F3];

// ---------------- CSR build ------------------------------------------------
__global__ void deg_init_kernel(int gi) {
    int i = blockIdx.x * 256 + threadIdx.x;
    if (i < NN) { g_deg[gi][i] = 0; g_cur[gi][i] = 0; }
}

__global__ void deg_count_kernel(int gi, const int* __restrict__ dst) {
    int e = blockIdx.x * 256 + threadIdx.x;
    if (e < EE) atomicAdd(&g_deg[gi][dst[e]], 1);
}

__global__ void scan1_kernel(int gi) {
    __shared__ int sh[256];
    int t = threadIdx.x;
    int i = blockIdx.x * 256 + t;
    int v = (i < NN) ? g_deg[gi][i] : 0;
    sh[t] = v;
    __syncthreads();
#pragma unroll
    for (int off = 1; off < 256; off <<= 1) {
        int x = (t >= off) ? sh[t - off] : 0;
        __syncthreads();
        sh[t] += x;
        __syncthreads();
    }
    if (i < NN) g_scanTmp[gi][i] = sh[t];
    if (t == 255) g_bsum[gi][blockIdx.x] = sh[255];
}

__global__ void scan2_kernel(int gi) {
    __shared__ int sh[256];
    int t = threadIdx.x;
    int v = (t < NB) ? g_bsum[gi][t] : 0;
    sh[t] = v;
    __syncthreads();
#pragma unroll
    for (int off = 1; off < 256; off <<= 1) {
        int x = (t >= off) ? sh[t - off] : 0;
        __syncthreads();
        sh[t] += x;
        __syncthreads();
    }
    g_boff[gi][t] = sh[t] - v;   // exclusive
}

// rowptr (exclusive) + dinv fused
__global__ void scan3_kernel(int gi) {
    int i = blockIdx.x * 256 + threadIdx.x;
    if (i < NN) {
        int deg = g_deg[gi][i];
        g_rowptr[gi][i] = g_scanTmp[gi][i] - deg + g_boff[gi][blockIdx.x];
        g_dinv[gi][i]   = rsqrtf((float)(deg + 1));   // +1 self loop
    }
}

__global__ void place_kernel(int gi, const int* __restrict__ src,
                             const int* __restrict__ dst) {
    int e = blockIdx.x * 256 + threadIdx.x;
    if (e >= EE) return;
    int s = src[e];
    int d = dst[e];
    int pos = g_rowptr[gi][d] + atomicAdd(&g_cur[gi][d], 1);
    int2 rec;
    rec.x = s;
    rec.y = __float_as_int(g_dinv[gi][s] * g_dinv[gi][d]);
    g_csr[gi][pos] = rec;
}

// ---------------- dense linear (layer 1 only): H = X @ W, Fin=Fout=64 ------
__global__ void __launch_bounds__(256) gemm_kernel(const float* __restrict__ X,
                                                   const float* __restrict__ W,
                                                   float* __restrict__ H) {
    __shared__ float Ws[64 * 64];
    __shared__ float Xs[16][65];

    int tid = threadIdx.y * 16 + threadIdx.x;
    for (int i = tid; i < 64 * 64; i += 256) Ws[i] = W[i];

    int r0 = blockIdx.x * 16;
    for (int i = tid; i < 16 * 64; i += 256) {
        int r = i >> 6, c = i & 63;
        Xs[r][c] = (r0 + r < NN) ? X[(r0 + r) * 64 + c] : 0.f;
    }
    __syncthreads();

    int row = r0 + threadIdx.y;
    if (row >= NN) return;

    float4 acc = make_float4(0.f, 0.f, 0.f, 0.f);
    const float4* Ws4 = (const float4*)Ws;
#pragma unroll
    for (int k = 0; k < 64; k++) {
        float xv = Xs[threadIdx.y][k];
        float4 wv = Ws4[k * 16 + threadIdx.x];
        acc.x = fmaf(xv, wv.x, acc.x);
        acc.y = fmaf(xv, wv.y, acc.y);
        acc.z = fmaf(xv, wv.z, acc.z);
        acc.w = fmaf(xv, wv.w, acc.w);
    }
    ((float4*)(H + row * 64))[threadIdx.x] = acc;
}

// ---------------- fused: a = relu(agg(H)+bias);  Out = a @ W ---------------
// One warp per node; 8 warps/block. Lane holds row elements {2*lane, 2*lane+1}.
template<int FOUT>
__global__ void __launch_bounds__(256) aggmm_kernel(int gi,
        const float* __restrict__ H, const float* __restrict__ bias,
        const float* __restrict__ W, float* __restrict__ Out) {
    __shared__ float Ws[64 * FOUT];
    __shared__ float Row[8][64];

    int tid = threadIdx.x;
    for (int i = tid; i < 64 * FOUT; i += 256) Ws[i] = W[i];
    __syncthreads();

    int warp = tid >> 5, lane = tid & 31;
    int n = blockIdx.x * 8 + warp;
    if (n >= NN) return;

    const int2* eb = g_csr[gi] + g_rowptr[gi][n];
    int cnt  = g_deg[gi][n];
    float d  = g_dinv[gi][n];
    float d2 = d * d;

    float2 acc = __ldg((const float2*)(H + n * 64) + lane);
    acc.x *= d2; acc.y *= d2;

    int i = 0;
    for (; i + 4 <= cnt; i += 4) {
        int2 e0 = __ldg(eb + i);
        int2 e1 = __ldg(eb + i + 1);
        int2 e2 = __ldg(eb + i + 2);
        int2 e3 = __ldg(eb + i + 3);
        float2 h0 = __ldg((const float2*)(H + e0.x * 64) + lane);
        float2 h1 = __ldg((const float2*)(H + e1.x * 64) + lane);
        float2 h2 = __ldg((const float2*)(H + e2.x * 64) + lane);
        float2 h3 = __ldg((const float2*)(H + e3.x * 64) + lane);
        float w0 = __int_as_float(e0.y), w1 = __int_as_float(e1.y);
        float w2 = __int_as_float(e2.y), w3 = __int_as_float(e3.y);
        acc.x = fmaf(w0, h0.x, acc.x); acc.y = fmaf(w0, h0.y, acc.y);
        acc.x = fmaf(w1, h1.x, acc.x); acc.y = fmaf(w1, h1.y, acc.y);
        acc.x = fmaf(w2, h2.x, acc.x); acc.y = fmaf(w2, h2.y, acc.y);
        acc.x = fmaf(w3, h3.x, acc.x); acc.y = fmaf(w3, h3.y, acc.y);
    }
    for (; i < cnt; i++) {
        int2 e0 = __ldg(eb + i);
        float2 h0 = __ldg((const float2*)(H + e0.x * 64) + lane);
        float w0 = __int_as_float(e0.y);
        acc.x = fmaf(w0, h0.x, acc.x); acc.y = fmaf(w0, h0.y, acc.y);
    }

    float2 b = __ldg((const float2*)bias + lane);
    acc.x = fmaxf(acc.x + b.x, 0.f);
    acc.y = fmaxf(acc.y + b.y, 0.f);
    Row[warp][2 * lane]     = acc.x;
    Row[warp][2 * lane + 1] = acc.y;
    __syncwarp();

    const float* r = Row[warp];
    if (FOUT == 64) {
        float2 o = make_float2(0.f, 0.f);
#pragma unroll
        for (int k = 0; k < 64; k++) {
            float xk = r[k];
            float2 wv = ((const float2*)(Ws + k * 64))[lane];
            o.x = fmaf(xk, wv.x, o.x);
            o.y = fmaf(xk, wv.y, o.y);
        }
        ((float2*)(Out + n * 64))[lane] = o;
    } else {   // FOUT == 32
        float o = 0.f;
#pragma unroll
        for (int k = 0; k < 64; k++)
            o = fmaf(r[k], Ws[k * 32 + lane], o);
        Out[n * 32 + lane] = o;
    }
}

// ---------------- final layer agg (F=32, +bias, no relu) -------------------
__global__ void __launch_bounds__(256) aggfinal_kernel(int gi,
        const float* __restrict__ H, const float* __restrict__ bias,
        float* __restrict__ Out) {
    int gwarp = (blockIdx.x * 256 + threadIdx.x) >> 5;
    int lane  = threadIdx.x & 31;
    if (gwarp >= NN) return;
    int n = gwarp;

    const int2* eb = g_csr[gi] + g_rowptr[gi][n];
    int cnt  = g_deg[gi][n];
    float d  = g_dinv[gi][n];

    float acc = __ldg(H + n * 32 + lane) * d * d;
    int i = 0;
    for (; i + 4 <= cnt; i += 4) {
        int2 e0 = __ldg(eb + i);
        int2 e1 = __ldg(eb + i + 1);
        int2 e2 = __ldg(eb + i + 2);
        int2 e3 = __ldg(eb + i + 3);
        float h0 = __ldg(H + e0.x * 32 + lane);
        float h1 = __ldg(H + e1.x * 32 + lane);
        float h2 = __ldg(H + e2.x * 32 + lane);
        float h3 = __ldg(H + e3.x * 32 + lane);
        acc = fmaf(__int_as_float(e0.y), h0, acc);
        acc = fmaf(__int_as_float(e1.y), h1, acc);
        acc = fmaf(__int_as_float(e2.y), h2, acc);
        acc = fmaf(__int_as_float(e3.y), h3, acc);
    }
    for (; i < cnt; i++) {
        int2 e0 = __ldg(eb + i);
        acc = fmaf(__int_as_float(e0.y), __ldg(H + e0.x * 32 + lane), acc);
    }
    Out[n * 32 + lane] = acc + __ldg(bias + lane);
}

// ---------------- attention pooling ----------------------------------------
__global__ void zero_small_kernel() {
    int t = threadIdx.x;      // 128 threads
    if (t < 64)      ((float*)g_m)[t] = 0.f;
    else             ((float*)g_pool)[t - 64] = 0.f;
}

__global__ void colsum_kernel(int gi, const float* __restrict__ A) {
    __shared__ float sh[8][F3];
    int j = threadIdx.x, ty = threadIdx.y;
    float acc = 0.f;
    for (int r = blockIdx.x * 8 + ty; r < NN; r += gridDim.x * 8)
        acc += A[r * F3 + j];
    sh[ty][j] = acc;
    __syncthreads();
    if (ty == 0) {
        float s = 0.f;
#pragma unroll
        for (int t = 0; t < 8; t++) s += sh[t][j];
        atomicAdd(&g_m[gi][j], s);
    }
}

__global__ void ctx_kernel(const float* __restrict__ Watt) {
    int t = threadIdx.x;          // 64 threads: gi = t>>5, j = t&31
    int gi = t >> 5, j = t & 31;
    float acc = 0.f;
#pragma unroll
    for (int k = 0; k < F3; k++)
        acc += g_m[gi][k] * (1.0f / NN) * Watt[k * F3 + j];
    g_ctx[gi][j] = tanhf(acc);
}

__global__ void __launch_bounds__(256) attpool_kernel(int gi, const float* __restrict__ A) {
    __shared__ float sp[F3];
    int tid = threadIdx.x;
    if (tid < F3) sp[tid] = 0.f;
    __syncthreads();

    float ctx[F3];
#pragma unroll
    for (int j = 0; j < F3; j++) ctx[j] = g_ctx[gi][j];

    float acc[F3];
#pragma unroll
    for (int j = 0; j < F3; j++) acc[j] = 0.f;

    for (int r = blockIdx.x * blockDim.x + tid; r < NN; r += gridDim.x * blockDim.x) {
        const float4* row = (const float4*)(A + r * F3);
        float rv[F3];
        float dot = 0.f;
#pragma unroll
        for (int q = 0; q < F3 / 4; q++) {
            float4 v = __ldg(row + q);
            rv[q * 4 + 0] = v.x; rv[q * 4 + 1] = v.y;
            rv[q * 4 + 2] = v.z; rv[q * 4 + 3] = v.w;
            dot = fmaf(v.x, ctx[q * 4 + 0], dot);
            dot = fmaf(v.y, ctx[q * 4 + 1], dot);
            dot = fmaf(v.z, ctx[q * 4 + 2], dot);
            dot = fmaf(v.w, ctx[q * 4 + 3], dot);
        }
        float s = 1.f / (1.f + expf(-dot));
#pragma unroll
        for (int j = 0; j < F3; j++) acc[j] = fmaf(rv[j], s, acc[j]);
    }
#pragma unroll
    for (int j = 0; j < F3; j++) atomicAdd(&sp[j], acc[j]);
    __syncthreads();
    if (tid < F3) atomicAdd(&g_pool[gi][tid], sp[tid]);
}

// ---------------- NTN scoring (512 threads, parallel over k and i) ---------
__global__ void __launch_bounds__(512) ntn_kernel(const float* __restrict__ Wtn,
                                                  const float* __restrict__ Wb,
                                                  const float* __restrict__ btn,
                                                  float* __restrict__ out) {
    __shared__ float e1[F3], e2[F3];
    __shared__ float red[512];
    int tid = threadIdx.x;
    if (tid < F3)           e1[tid] = g_pool[0][tid];
    else if (tid < 2 * F3)  e2[tid - F3] = g_pool[1][tid - F3];
    __syncthreads();

    int k  = tid & 15;     // 0..15
    int ic = tid >> 4;     // 0..31  (i index)
    float a = e1[ic];
    float s = 0.f;
#pragma unroll
    for (int j = 0; j < F3; j++)
        s = fmaf(a * e2[j], __ldg(&Wtn[(ic * F3 + j) * KK + k]), s);
    red[tid] = s;
    __syncthreads();
#pragma unroll
    for (int off = 256; off >= 16; off >>= 1) {
        if (tid < off) red[tid] += red[tid + off];
        __syncthreads();
    }
    if (tid < KK) {
        float bl = 0.f;
#pragma unroll
        for (int i = 0; i < F3; i++)
            bl += Wb[tid * 64 + i] * e1[i] + Wb[tid * 64 + F3 + i] * e2[i];
        float v = red[tid] + bl + btn[tid];
        out[tid] = v > 0.f ? v : 0.f;
    }
}

// ---------------- driver ----------------------------------------------------
extern "C" void kernel_launch(void* const* d_in, const int* in_sizes, int n_in,
                              void* d_out, int out_size) {
    const float* feats[2] = { (const float*)d_in[0], (const float*)d_in[2] };
    const int*   edges[2] = { (const int*)d_in[1],   (const int*)d_in[3]   };
    const float* W1   = (const float*)d_in[4];
    const float* b1   = (const float*)d_in[5];
    const float* W2   = (const float*)d_in[6];
    const float* b2   = (const float*)d_in[7];
    const float* W3   = (const float*)d_in[8];
    const float* b3   = (const float*)d_in[9];
    const float* Watt = (const float*)d_in[10];
    const float* Wtn  = (const float*)d_in[11];
    const float* Wb   = (const float*)d_in[12];
    const float* btn  = (const float*)d_in[13];
    float* out = (float*)d_out;

    const int nb_node = NB;                       // 196
    const int nb_edge = (EE + 255) / 256;         // 3125
    const int nb_agg  = (NN + 7) / 8;             // 6250 (warp per node)

    const int* src[2] = { edges[0], edges[1] };
    const int* dst[2] = { edges[0] + EE, edges[1] + EE };

    // --- CSR builds interleaved (launch idx 3 = deg_count(1) for ncu) ---
    deg_init_kernel<<<nb_node, 256>>>(0);                 // 0
    deg_init_kernel<<<nb_node, 256>>>(1);                 // 1
    deg_count_kernel<<<nb_edge, 256>>>(0, dst[0]);        // 2
    deg_count_kernel<<<nb_edge, 256>>>(1, dst[1]);        // 3  <- ncu sample
    scan1_kernel<<<nb_node, 256>>>(0);
    scan1_kernel<<<nb_node, 256>>>(1);
    scan2_kernel<<<1, 256>>>(0);
    scan2_kernel<<<1, 256>>>(1);
    scan3_kernel<<<nb_node, 256>>>(0);
    scan3_kernel<<<nb_node, 256>>>(1);
    place_kernel<<<nb_edge, 256>>>(0, src[0], dst[0]);
    place_kernel<<<nb_edge, 256>>>(1, src[1], dst[1]);

    // --- layer 1 gemm: t1 = X @ W1 ---
    gemm_kernel<<<(NN + 15) / 16, dim3(16, 16)>>>(feats[0], W1, g_P[0]);
    gemm_kernel<<<(NN + 15) / 16, dim3(16, 16)>>>(feats[1], W1, g_P[1]);

    // --- fused: a1 = relu(agg(t1)+b1); t2 = a1 @ W2 ---
    aggmm_kernel<64><<<nb_agg, 256>>>(0, g_P[0], b1, W2, g_Q[0]);
    aggmm_kernel<64><<<nb_agg, 256>>>(1, g_P[1], b1, W2, g_Q[1]);

    // --- fused: a2 = relu(agg(t2)+b2); t3 = a2 @ W3 ---
    aggmm_kernel<32><<<nb_agg, 256>>>(0, g_Q[0], b2, W3, g_P[0]);
    aggmm_kernel<32><<<nb_agg, 256>>>(1, g_Q[1], b2, W3, g_P[1]);

    // --- a3 = agg(t3)+b3 ---
    aggfinal_kernel<<<nb_agg, 256>>>(0, g_P[0], b3, g_Q[0]);
    aggfinal_kernel<<<nb_agg, 256>>>(1, g_P[1], b3, g_Q[1]);

    // --- attention pooling ---
    zero_small_kernel<<<1, 128>>>();
    colsum_kernel<<<128, dim3(32, 8)>>>(0, g_Q[0]);
    colsum_kernel<<<128, dim3(32, 8)>>>(1, g_Q[1]);
    ctx_kernel<<<1, 64>>>(Watt);
    attpool_kernel<<<208, 256>>>(0, g_Q[0]);
    attpool_kernel<<<208, 256>>>(1, g_Q[1]);

    ntn_kernel<<<1, 512>>>(Wtn, Wb, btn, out);
}

// round 7
// speedup vs baseline: 17.4639x; 17.4639x over previous
#include <cuda_runtime.h>
#include <math.h>

// Problem constants (fixed by the reference)
#define NN   50000
#define EE   800000
#define F3   32
#define KK   16
#define NN2  (2*NN)                    // 100000 nodes total
#define EE2  (2*EE)                    // 1.6M edges total
#define NBLK 592                       // 148 SMs * 4 blocks (guaranteed resident)
#define NTHREAD 256
#define NTH_TOT (NBLK*NTHREAD)
#define NWARP_TOT (NBLK*8)
#define NCHUNK ((NN2+255)/256)         // 391 scan chunks
#define FULLMASK 0xffffffffu

// ---------------- scratch (__device__ globals; no allocs allowed) ----------
__device__ float g_P[NN2*64];          // activations ping (per-graph halves)
__device__ float g_Q[NN2*64];          // activations pong
__device__ int2  g_csr[EE2];           // flat CSR records {src_local, bits(w)}
__device__ int   g_rowptr[NN2];        // global flat row offsets into g_csr
__device__ int   g_deg[NN2];
__device__ int   g_cur[NN2];
__device__ int   g_scanTmp[NN2];
__device__ int   g_bsum[NCHUNK];
__device__ int   g_boff[NCHUNK];
__device__ float g_dinv[NN2];
__device__ float g_m[2][F3];
__device__ float g_ctx[2][F3];
__device__ float g_pool[2][F3];
__device__ unsigned g_bar_cnt = 0;
__device__ unsigned g_bar_gen = 0;

// ---------------- software grid barrier (all NBLK blocks resident) ---------
__device__ __forceinline__ void gridsync() {
    __syncthreads();
    if (threadIdx.x == 0) {
        __threadfence();
        unsigned gen = *(volatile unsigned*)&g_bar_gen;
        if (atomicAdd(&g_bar_cnt, 1u) == NBLK - 1) {
            atomicExch(&g_bar_cnt, 0u);
            __threadfence();
            *(volatile unsigned*)&g_bar_gen = gen + 1u;
        } else {
            while (*(volatile unsigned*)&g_bar_gen == gen) { }
        }
        __threadfence();
    }
    __syncthreads();
}

// ---------------- the whole SimGNN forward in one kernel --------------------
__global__ void __launch_bounds__(NTHREAD, 4) mega_kernel(
    const float* __restrict__ f0, const int* __restrict__ e0,
    const float* __restrict__ f1, const int* __restrict__ e1,
    const float* __restrict__ W1, const float* __restrict__ b1,
    const float* __restrict__ W2, const float* __restrict__ b2,
    const float* __restrict__ W3, const float* __restrict__ b3,
    const float* __restrict__ Watt,
    const float* __restrict__ Wtn, const float* __restrict__ Wb,
    const float* __restrict__ btn, float* __restrict__ out)
{
    __shared__ __align__(16) char smem_raw[21504];
    float* Ws = (float*)smem_raw;                         // up to 16 KB weights

    const int tid   = threadIdx.x;
    const int bid   = blockIdx.x;
    const int gtid  = bid * NTHREAD + tid;
    const int warp  = tid >> 5, lane = tid & 31;
    const int gwarp = bid * 8 + warp;

    const int*   edge[2] = { e0, e1 };
    const float* feat[2] = { f0, f1 };

    // ---- P0: init ----------------------------------------------------------
    for (int i = gtid; i < NN2; i += NTH_TOT) { g_deg[i] = 0; g_cur[i] = 0; }
    if (gtid < 64) { ((float*)g_m)[gtid] = 0.f; ((float*)g_pool)[gtid] = 0.f; }
    gridsync();

    // ---- P1: degree count --------------------------------------------------
    for (int e = gtid; e < EE2; e += NTH_TOT) {
        int gi = e >= EE;
        int le = e - gi * EE;
        int d  = edge[gi][EE + le];                  // dst row
        atomicAdd(&g_deg[gi * NN + d], 1);
    }
    gridsync();

    // ---- P2: per-chunk inclusive scan (256 elems/chunk) --------------------
    {
        int* sh = (int*)smem_raw;
        for (int c = bid; c < NCHUNK; c += NBLK) {
            int i = c * 256 + tid;
            int v = (i < NN2) ? g_deg[i] : 0;
            sh[tid] = v;
            __syncthreads();
#pragma unroll
            for (int off = 1; off < 256; off <<= 1) {
                int x = (tid >= off) ? sh[tid - off] : 0;
                __syncthreads();
                sh[tid] += x;
                __syncthreads();
            }
            if (i < NN2) g_scanTmp[i] = sh[tid];
            if (tid == 255) g_bsum[c] = sh[255];
            __syncthreads();
        }
    }
    gridsync();

    // ---- P3: scan chunk totals (block 0, warp 0, serial-carry) -------------
    if (bid == 0 && warp == 0) {
        int carry = 0;
        for (int base = 0; base < NCHUNK; base += 32) {
            int idx = base + lane;
            int v = (idx < NCHUNK) ? g_bsum[idx] : 0;
            int orig = v;
#pragma unroll
            for (int o = 1; o < 32; o <<= 1) {
                int t2 = __shfl_up_sync(FULLMASK, v, o);
                if (lane >= o) v += t2;
            }
            if (idx < NCHUNK) g_boff[idx] = carry + v - orig;   // exclusive
            carry += __shfl_sync(FULLMASK, v, 31);
        }
    }
    gridsync();

    // ---- P4: rowptr + dinv -------------------------------------------------
    for (int i = gtid; i < NN2; i += NTH_TOT) {
        int d = g_deg[i];
        g_rowptr[i] = g_scanTmp[i] - d + g_boff[i >> 8];
        g_dinv[i]   = rsqrtf((float)(d + 1));        // +1 self loop
    }
    gridsync();

    // ---- P5: CSR placement -------------------------------------------------
    for (int e = gtid; e < EE2; e += NTH_TOT) {
        int gi = e >= EE;
        int le = e - gi * EE;
        int s = edge[gi][le];
        int d = edge[gi][EE + le];
        int gd = gi * NN + d;
        int pos = g_rowptr[gd] + atomicAdd(&g_cur[gd], 1);
        int2 rec;
        rec.x = s;
        rec.y = __float_as_int(g_dinv[gi * NN + s] * g_dinv[gd]);
        g_csr[pos] = rec;
    }
    gridsync();

    // ---- P6: layer-1 gemm  t1 = X @ W1  -> g_P (64-wide) -------------------
    {
        float (*Xs)[65] = (float(*)[65])(smem_raw + 16384);
        for (int i = tid; i < 4096; i += 256) Ws[i] = W1[i];
        __syncthreads();
        int tx = tid & 15, ty = tid >> 4;
        for (int tt = bid; tt < 6250; tt += NBLK) {       // 2 * 3125 row tiles
            int gi = tt >= 3125;
            int r0 = (tt - gi * 3125) * 16;
            const float* X = feat[gi];
            for (int i = tid; i < 16 * 64; i += 256) {
                int r = i >> 6, c = i & 63;
                Xs[r][c] = (r0 + r < NN) ? X[(r0 + r) * 64 + c] : 0.f;
            }
            __syncthreads();
            int row = r0 + ty;
            if (row < NN) {
                float4 acc = make_float4(0.f, 0.f, 0.f, 0.f);
                const float4* Ws4 = (const float4*)Ws;
#pragma unroll
                for (int k = 0; k < 64; k++) {
                    float xv = Xs[ty][k];
                    float4 wv = Ws4[k * 16 + tx];
                    acc.x = fmaf(xv, wv.x, acc.x);
                    acc.y = fmaf(xv, wv.y, acc.y);
                    acc.z = fmaf(xv, wv.z, acc.z);
                    acc.w = fmaf(xv, wv.w, acc.w);
                }
                ((float4*)(g_P + (gi * NN + row) * 64))[tx] = acc;
            }
            __syncthreads();
        }
    }
    gridsync();

    // ---- P7: t2 = relu(agg(t1)+b1) @ W2  (g_P -> g_Q, 64-wide) -------------
    {
        float (*Row)[64] = (float(*)[64])(smem_raw + 16384);
        for (int i = tid; i < 4096; i += 256) Ws[i] = W2[i];
        __syncthreads();
        float2 bb = ((const float2*)b1)[lane];
        for (int nf = gwarp; nf < NN2; nf += NWARP_TOT) {
            int gi = nf >= NN;
            int n  = nf - gi * NN;
            const float* H = g_P + gi * NN * 64;
            const int2* eb = g_csr + g_rowptr[nf];
            int cnt  = g_deg[nf];
            float dv = g_dinv[nf];
            float2 acc = ((const float2*)(H + n * 64))[lane];
            float d2 = dv * dv;
            acc.x *= d2; acc.y *= d2;
            int i = 0;
            for (; i + 4 <= cnt; i += 4) {
                int2 r0 = __ldg(eb + i),     r1 = __ldg(eb + i + 1);
                int2 r2 = __ldg(eb + i + 2), r3 = __ldg(eb + i + 3);
                float2 h0 = __ldg((const float2*)(H + r0.x * 64) + lane);
                float2 h1 = __ldg((const float2*)(H + r1.x * 64) + lane);
                float2 h2 = __ldg((const float2*)(H + r2.x * 64) + lane);
                float2 h3 = __ldg((const float2*)(H + r3.x * 64) + lane);
                acc.x = fmaf(__int_as_float(r0.y), h0.x, acc.x); acc.y = fmaf(__int_as_float(r0.y), h0.y, acc.y);
                acc.x = fmaf(__int_as_float(r1.y), h1.x, acc.x); acc.y = fmaf(__int_as_float(r1.y), h1.y, acc.y);
                acc.x = fmaf(__int_as_float(r2.y), h2.x, acc.x); acc.y = fmaf(__int_as_float(r2.y), h2.y, acc.y);
                acc.x = fmaf(__int_as_float(r3.y), h3.x, acc.x); acc.y = fmaf(__int_as_float(r3.y), h3.y, acc.y);
            }
            for (; i < cnt; i++) {
                int2 r0 = __ldg(eb + i);
                float2 h0 = __ldg((const float2*)(H + r0.x * 64) + lane);
                acc.x = fmaf(__int_as_float(r0.y), h0.x, acc.x);
                acc.y = fmaf(__int_as_float(r0.y), h0.y, acc.y);
            }
            acc.x = fmaxf(acc.x + bb.x, 0.f);
            acc.y = fmaxf(acc.y + bb.y, 0.f);
            Row[warp][2 * lane]     = acc.x;
            Row[warp][2 * lane + 1] = acc.y;
            __syncwarp();
            const float* r = Row[warp];
            float2 o = make_float2(0.f, 0.f);
#pragma unroll
            for (int k = 0; k < 64; k++) {
                float xk = r[k];
                float2 wv = ((const float2*)(Ws + k * 64))[lane];
                o.x = fmaf(xk, wv.x, o.x);
                o.y = fmaf(xk, wv.y, o.y);
            }
            ((float2*)(g_Q + gi * NN * 64 + n * 64))[lane] = o;
            __syncwarp();
        }
    }
    gridsync();

    // ---- P8: t3 = relu(agg(t2)+b2) @ W3  (g_Q -> g_P, 32-wide rows) --------
    {
        float (*Row)[64] = (float(*)[64])(smem_raw + 16384);
        for (int i = tid; i < 2048; i += 256) Ws[i] = W3[i];
        __syncthreads();
        float2 bb = ((const float2*)b2)[lane];
        for (int nf = gwarp; nf < NN2; nf += NWARP_TOT) {
            int gi = nf >= NN;
            int n  = nf - gi * NN;
            const float* H = g_Q + gi * NN * 64;
            const int2* eb = g_csr + g_rowptr[nf];
            int cnt  = g_deg[nf];
            float dv = g_dinv[nf];
            float2 acc = ((const float2*)(H + n * 64))[lane];
            float d2 = dv * dv;
            acc.x *= d2; acc.y *= d2;
            int i = 0;
            for (; i + 4 <= cnt; i += 4) {
                int2 r0 = __ldg(eb + i),     r1 = __ldg(eb + i + 1);
                int2 r2 = __ldg(eb + i + 2), r3 = __ldg(eb + i + 3);
                float2 h0 = __ldg((const float2*)(H + r0.x * 64) + lane);
                float2 h1 = __ldg((const float2*)(H + r1.x * 64) + lane);
                float2 h2 = __ldg((const float2*)(H + r2.x * 64) + lane);
                float2 h3 = __ldg((const float2*)(H + r3.x * 64) + lane);
                acc.x = fmaf(__int_as_float(r0.y), h0.x, acc.x); acc.y = fmaf(__int_as_float(r0.y), h0.y, acc.y);
                acc.x = fmaf(__int_as_float(r1.y), h1.x, acc.x); acc.y = fmaf(__int_as_float(r1.y), h1.y, acc.y);
                acc.x = fmaf(__int_as_float(r2.y), h2.x, acc.x); acc.y = fmaf(__int_as_float(r2.y), h2.y, acc.y);
                acc.x = fmaf(__int_as_float(r3.y), h3.x, acc.x); acc.y = fmaf(__int_as_float(r3.y), h3.y, acc.y);
            }
            for (; i < cnt; i++) {
                int2 r0 = __ldg(eb + i);
                float2 h0 = __ldg((const float2*)(H + r0.x * 64) + lane);
                acc.x = fmaf(__int_as_float(r0.y), h0.x, acc.x);
                acc.y = fmaf(__int_as_float(r0.y), h0.y, acc.y);
            }
            acc.x = fmaxf(acc.x + bb.x, 0.f);
            acc.y = fmaxf(acc.y + bb.y, 0.f);
            Row[warp][2 * lane]     = acc.x;
            Row[warp][2 * lane + 1] = acc.y;
            __syncwarp();
            const float* r = Row[warp];
            float o = 0.f;
#pragma unroll
            for (int k = 0; k < 64; k++)
                o = fmaf(r[k], Ws[k * 32 + lane], o);
            g_P[gi * NN * 64 + n * 32 + lane] = o;
            __syncwarp();
        }
    }
    gridsync();

    // ---- P9: a3 = agg(t3)+b3 (g_P -> g_Q, 32-wide) + fused column sums -----
    {
        float* part = (float*)(smem_raw + 16384);          // [2][32]
        if (tid < 64) part[tid] = 0.f;
        __syncthreads();
        float bv = __ldg(b3 + lane);
        float cs0 = 0.f, cs1 = 0.f;
        for (int nf = gwarp; nf < NN2; nf += NWARP_TOT) {
            int gi = nf >= NN;
            int n  = nf - gi * NN;
            const float* H = g_P + gi * NN * 64;           // 32-wide rows
            const int2* eb = g_csr + g_rowptr[nf];
            int cnt  = g_deg[nf];
            float dv = g_dinv[nf];
            float acc = __ldg(H + n * 32 + lane) * dv * dv;
            int i = 0;
            for (; i + 4 <= cnt; i += 4) {
                int2 r0 = __ldg(eb + i),     r1 = __ldg(eb + i + 1);
                int2 r2 = __ldg(eb + i + 2), r3 = __ldg(eb + i + 3);
                float h0 = __ldg(H + r0.x * 32 + lane);
                float h1 = __ldg(H + r1.x * 32 + lane);
                float h2 = __ldg(H + r2.x * 32 + lane);
                float h3 = __ldg(H + r3.x * 32 + lane);
                acc = fmaf(__int_as_float(r0.y), h0, acc);
                acc = fmaf(__int_as_float(r1.y), h1, acc);
                acc = fmaf(__int_as_float(r2.y), h2, acc);
                acc = fmaf(__int_as_float(r3.y), h3, acc);
            }
            for (; i < cnt; i++) {
                int2 r0 = __ldg(eb + i);
                acc = fmaf(__int_as_float(r0.y), __ldg(H + r0.x * 32 + lane), acc);
            }
            acc += bv;
            g_Q[gi * NN * 64 + n * 32 + lane] = acc;
            if (gi) cs1 += acc; else cs0 += acc;
        }
        atomicAdd(&part[lane],      cs0);
        atomicAdd(&part[32 + lane], cs1);
        __syncthreads();
        if (tid < 64) atomicAdd(&((float*)g_m)[tid], part[tid]);
    }
    gridsync();

    // ---- P10: ctx = tanh(mean @ Watt) (block 0) ----------------------------
    if (bid == 0 && tid < 64) {
        int gi = tid >> 5, j = tid & 31;
        float acc = 0.f;
#pragma unroll
        for (int k = 0; k < F3; k++)
            acc += g_m[gi][k] * (1.0f / NN) * Watt[k * F3 + j];
        g_ctx[gi][j] = tanhf(acc);
    }
    gridsync();

    // ---- P11: attention pool (warp per row, shfl reduce) -------------------
    {
        float c0 = g_ctx[0][lane], c1 = g_ctx[1][lane];
        float a0 = 0.f, a1 = 0.f;
        for (int nf = gwarp; nf < NN2; nf += NWARP_TOT) {
            int gi = nf >= NN;
            int n  = nf - gi * NN;
            float v = __ldg(g_Q + gi * NN * 64 + n * 32 + lane);
            float p = v * (gi ? c1 : c0);
#pragma unroll
            for (int o = 16; o >= 1; o >>= 1)
                p += __shfl_xor_sync(FULLMASK, p, o);
            float s = 1.f / (1.f + expf(-p));
            if (gi) a1 = fmaf(v, s, a1); else a0 = fmaf(v, s, a0);
        }
        float* part = (float*)(smem_raw + 16384);          // [2][32]
        if (tid < 64) part[tid] = 0.f;
        __syncthreads();
        atomicAdd(&part[lane],      a0);
        atomicAdd(&part[32 + lane], a1);
        __syncthreads();
        if (tid < 64) atomicAdd(&((float*)g_pool)[tid], part[tid]);
    }
    gridsync();

    // ---- P12: NTN scoring (block 0) ----------------------------------------
    if (bid == 0) {
        float* e12 = (float*)smem_raw;                     // 64 floats
        float* red = (float*)(smem_raw + 256);             // 256 floats
        if (tid < 64) e12[tid] = ((float*)g_pool)[tid];
        __syncthreads();
        int k = tid & 15, ih = tid >> 4;                   // ih: 0..15
        float s = 0.f;
#pragma unroll
        for (int half = 0; half < 2; half++) {
            int i = ih + half * 16;
            float a = e12[i];
            for (int j = 0; j < F3; j++)
                s = fmaf(a * e12[32 + j], __ldg(&Wtn[(i * F3 + j) * KK + k]), s);
        }
        red[tid] = s;
        __syncthreads();
#pragma unroll
        for (int off = 128; off >= 16; off >>= 1) {
            if (tid < off) red[tid] += red[tid + off];
            __syncthreads();
        }
        if (tid < KK) {
            float bl = 0.f;
#pragma unroll
            for (int i = 0; i < 64; i++)
                bl += Wb[tid * 64 + i] * e12[i];
            float v = red[tid] + bl + btn[tid];
            out[tid] = v > 0.f ? v : 0.f;
        }
    }
}

// ---------------- driver ----------------------------------------------------
extern "C" void kernel_launch(void* const* d_in, const int* in_sizes, int n_in,
                              void* d_out, int out_size) {
    mega_kernel<<<NBLK, NTHREAD>>>(
        (const float*)d_in[0], (const int*)d_in[1],
        (const float*)d_in[2], (const int*)d_in[3],
        (const float*)d_in[4], (const float*)d_in[5],
        (const float*)d_in[6], (const float*)d_in[7],
        (const float*)d_in[8], (const float*)d_in[9],
        (const float*)d_in[10],
        (const float*)d_in[11], (const float*)d_in[12],
        (const float*)d_in[13], (float*)d_out);
}

// round 12
// speedup vs baseline: 18.0399x; 1.0330x over previous
#include <cuda_runtime.h>
#include <math.h>

// Problem constants (fixed by the reference)
#define NN   50000
#define EE   800000
#define F3   32
#define KK   16
#define NN2  (2*NN)                    // 100000 nodes total
#define EE2  (2*EE)                    // 1.6M edges total
#define NBLK 592                       // 148 SMs * 4 blocks (guaranteed resident)
#define NTHREAD 256
#define NTH_TOT (NBLK*NTHREAD)
#define NWARP_TOT (NBLK*8)
#define NCHUNK ((NN2+255)/256)         // 391 scan chunks
#define FULLMASK 0xffffffffu

// ---------------- scratch (__device__ globals; no allocs allowed) ----------
__device__ float g_P[NN2*64];          // activations ping (per-graph halves)
__device__ float g_Q[NN2*64];          // activations pong
__device__ int2  g_csr[EE2];           // flat CSR records {src_local, bits(w)}
__device__ int   g_rowptr[NN2];        // global flat row offsets into g_csr
__device__ int   g_deg[NN2];
__device__ int   g_cur[NN2];
__device__ int   g_scanTmp[NN2];
__device__ int   g_bsum[NCHUNK];
__device__ int   g_boff[NCHUNK];
__device__ float g_dinv[NN2];
__device__ float g_m[2][F3];
__device__ float g_pool[2][F3];
__device__ unsigned g_bar_cnt = 0;
__device__ unsigned g_bar_gen = 0;

// ---------------- software grid barrier (all NBLK blocks resident) ---------
__device__ __forceinline__ void gridsync() {
    __syncthreads();
    if (threadIdx.x == 0) {
        __threadfence();
        unsigned gen = *(volatile unsigned*)&g_bar_gen;
        if (atomicAdd(&g_bar_cnt, 1u) == NBLK - 1) {
            atomicExch(&g_bar_cnt, 0u);
            __threadfence();
            *(volatile unsigned*)&g_bar_gen = gen + 1u;
        } else {
            while (*(volatile unsigned*)&g_bar_gen == gen) { }
        }
        __threadfence();
    }
    __syncthreads();
}

// ---------------- the whole SimGNN forward in one kernel --------------------
__global__ void __launch_bounds__(NTHREAD, 4) mega_kernel(
    const float* __restrict__ f0, const int* __restrict__ e0,
    const float* __restrict__ f1, const int* __restrict__ e1,
    const float* __restrict__ W1, const float* __restrict__ b1,
    const float* __restrict__ W2, const float* __restrict__ b2,
    const float* __restrict__ W3, const float* __restrict__ b3,
    const float* __restrict__ Watt,
    const float* __restrict__ Wtn, const float* __restrict__ Wb,
    const float* __restrict__ btn, float* __restrict__ out)
{
    __shared__ __align__(16) char smem_raw[21504];
    float* Ws = (float*)smem_raw;                         // up to 16 KB weights

    const int tid   = threadIdx.x;
    const int bid   = blockIdx.x;
    const int gtid  = bid * NTHREAD + tid;
    const int warp  = tid >> 5, lane = tid & 31;
    const int gwarp = bid * 8 + warp;
    const int half  = lane >> 4;       // dual-edge half id
    const int l4    = lane & 15;       // column group within half

    const int*   edge[2] = { e0, e1 };
    const float* feat[2] = { f0, f1 };

    // ---- P0: init ----------------------------------------------------------
    for (int i = gtid; i < NN2; i += NTH_TOT) { g_deg[i] = 0; g_cur[i] = 0; }
    if (gtid < 64) { ((float*)g_m)[gtid] = 0.f; ((float*)g_pool)[gtid] = 0.f; }
    gridsync();

    // ---- P1: degree count (int4-vectorized) --------------------------------
    for (int e4 = gtid; e4 < EE2 / 4; e4 += NTH_TOT) {
        int gi = e4 >= EE / 4;
        int l  = e4 - gi * (EE / 4);
        int4 d = __ldg((const int4*)(edge[gi] + EE) + l);
        int* dg = g_deg + gi * NN;
        atomicAdd(dg + d.x, 1); atomicAdd(dg + d.y, 1);
        atomicAdd(dg + d.z, 1); atomicAdd(dg + d.w, 1);
    }
    gridsync();

    // ---- P2: per-chunk inclusive scan (256 elems/chunk) --------------------
    {
        int* sh = (int*)smem_raw;
        for (int c = bid; c < NCHUNK; c += NBLK) {
            int i = c * 256 + tid;
            int v = (i < NN2) ? g_deg[i] : 0;
            sh[tid] = v;
            __syncthreads();
#pragma unroll
            for (int off = 1; off < 256; off <<= 1) {
                int x = (tid >= off) ? sh[tid - off] : 0;
                __syncthreads();
                sh[tid] += x;
                __syncthreads();
            }
            if (i < NN2) g_scanTmp[i] = sh[tid];
            if (tid == 255) g_bsum[c] = sh[255];
            __syncthreads();
        }
    }
    gridsync();

    // ---- P3: scan chunk totals (block 0, warp 0, serial-carry) -------------
    if (bid == 0 && warp == 0) {
        int carry = 0;
        for (int base = 0; base < NCHUNK; base += 32) {
            int idx = base + lane;
            int v = (idx < NCHUNK) ? g_bsum[idx] : 0;
            int orig = v;
#pragma unroll
            for (int o = 1; o < 32; o <<= 1) {
                int t2 = __shfl_up_sync(FULLMASK, v, o);
                if (lane >= o) v += t2;
            }
            if (idx < NCHUNK) g_boff[idx] = carry + v - orig;   // exclusive
            carry += __shfl_sync(FULLMASK, v, 31);
        }
    }
    gridsync();

    // ---- P4: rowptr + dinv -------------------------------------------------
    for (int i = gtid; i < NN2; i += NTH_TOT) {
        int d = g_deg[i];
        g_rowptr[i] = g_scanTmp[i] - d + g_boff[i >> 8];
        g_dinv[i]   = rsqrtf((float)(d + 1));        // +1 self loop
    }
    gridsync();

    // ---- P5: CSR placement (int4-vectorized loads) -------------------------
    for (int e4 = gtid; e4 < EE2 / 4; e4 += NTH_TOT) {
        int gi = e4 >= EE / 4;
        int l  = e4 - gi * (EE / 4);
        int4 s4 = __ldg((const int4*)(edge[gi]) + l);
        int4 d4 = __ldg((const int4*)(edge[gi] + EE) + l);
        const float* dv = g_dinv + gi * NN;
        int base = gi * NN;
#pragma unroll
        for (int u = 0; u < 4; u++) {
            int s = (u == 0) ? s4.x : (u == 1) ? s4.y : (u == 2) ? s4.z : s4.w;
            int d = (u == 0) ? d4.x : (u == 1) ? d4.y : (u == 2) ? d4.z : d4.w;
            int gd = base + d;
            int pos = g_rowptr[gd] + atomicAdd(&g_cur[gd], 1);
            int2 rec;
            rec.x = s;
            rec.y = __float_as_int(dv[s] * g_dinv[gd]);
            g_csr[pos] = rec;
        }
    }
    gridsync();

    // ---- P6: layer-1 gemm  t1 = X @ W1  -> g_P (64-wide) -------------------
    {
        float (*Xs)[65] = (float(*)[65])(smem_raw + 16384);
        for (int i = tid; i < 4096; i += 256) Ws[i] = W1[i];
        __syncthreads();
        int tx = tid & 15, ty = tid >> 4;
        for (int tt = bid; tt < 6250; tt += NBLK) {       // 2 * 3125 row tiles
            int gi = tt >= 3125;
            int r0 = (tt - gi * 3125) * 16;
            const float* X = feat[gi];
            for (int i = tid; i < 16 * 64; i += 256) {
                int r = i >> 6, c = i & 63;
                Xs[r][c] = (r0 + r < NN) ? X[(r0 + r) * 64 + c] : 0.f;
            }
            __syncthreads();
            int row = r0 + ty;
            if (row < NN) {
                float4 acc = make_float4(0.f, 0.f, 0.f, 0.f);
                const float4* Ws4 = (const float4*)Ws;
#pragma unroll
                for (int k = 0; k < 64; k++) {
                    float xv = Xs[ty][k];
                    float4 wv = Ws4[k * 16 + tx];
                    acc.x = fmaf(xv, wv.x, acc.x);
                    acc.y = fmaf(xv, wv.y, acc.y);
                    acc.z = fmaf(xv, wv.z, acc.z);
                    acc.w = fmaf(xv, wv.w, acc.w);
                }
                ((float4*)(g_P + (gi * NN + row) * 64))[tx] = acc;
            }
            __syncthreads();
        }
    }
    gridsync();

    // ==== P7 / P8: fused agg + gemm layers (64-wide input) ==================
    // Dual-edge half-warp: half A processes even edges (float4 cols 4*l4..),
    // half B odd edges. Combine with shfl_xor(16). Then smem-row epilogue gemm.
#define AGG64_BODY(SRC, BIASP)                                                \
    const float* H = SRC + gi * NN * 64;                                      \
    const int2* eb = g_csr + g_rowptr[nf];                                    \
    int cnt  = g_deg[nf];                                                     \
    float dv = g_dinv[nf];                                                    \
    float4 acc;                                                               \
    if (half == 0) {                                                          \
        float4 v = __ldg((const float4*)(H + n * 64) + l4);                   \
        float d2 = dv * dv;                                                   \
        acc.x = v.x * d2; acc.y = v.y * d2; acc.z = v.z * d2; acc.w = v.w * d2;\
    } else acc = make_float4(0.f, 0.f, 0.f, 0.f);                             \
    int base = 0;                                                             \
    for (; base + 8 <= cnt; base += 8) {                                      \
        int2 r0 = __ldg(eb + base     + half);                                \
        int2 r1 = __ldg(eb + base + 2 + half);                                \
        int2 r2 = __ldg(eb + base + 4 + half);                                \
        int2 r3 = __ldg(eb + base + 6 + half);                                \
        float4 v0 = __ldg((const float4*)(H + r0.x * 64) + l4);               \
        float4 v1 = __ldg((const float4*)(H + r1.x * 64) + l4);               \
        float4 v2 = __ldg((const float4*)(H + r2.x * 64) + l4);               \
        float4 v3 = __ldg((const float4*)(H + r3.x * 64) + l4);               \
        float w0 = __int_as_float(r0.y), w1 = __int_as_float(r1.y);           \
        float w2 = __int_as_float(r2.y), w3 = __int_as_float(r3.y);           \
        acc.x = fmaf(w0, v0.x, acc.x); acc.y = fmaf(w0, v0.y, acc.y);         \
        acc.z = fmaf(w0, v0.z, acc.z); acc.w = fmaf(w0, v0.w, acc.w);         \
        acc.x = fmaf(w1, v1.x, acc.x); acc.y = fmaf(w1, v1.y, acc.y);         \
        acc.z = fmaf(w1, v1.z, acc.z); acc.w = fmaf(w1, v1.w, acc.w);         \
        acc.x = fmaf(w2, v2.x, acc.x); acc.y = fmaf(w2, v2.y, acc.y);         \
        acc.z = fmaf(w2, v2.z, acc.z); acc.w = fmaf(w2, v2.w, acc.w);         \
        acc.x = fmaf(w3, v3.x, acc.x); acc.y = fmaf(w3, v3.y, acc.y);         \
        acc.z = fmaf(w3, v3.z, acc.z); acc.w = fmaf(w3, v3.w, acc.w);         \
    }                                                                         \
    for (; base < cnt; base += 2) {                                           \
        int idx = base + half;                                                \
        if (idx < cnt) {                                                      \
            int2 r0 = __ldg(eb + idx);                                        \
            float4 v0 = __ldg((const float4*)(H + r0.x * 64) + l4);           \
            float w0 = __int_as_float(r0.y);                                  \
            acc.x = fmaf(w0, v0.x, acc.x); acc.y = fmaf(w0, v0.y, acc.y);     \
            acc.z = fmaf(w0, v0.z, acc.z); acc.w = fmaf(w0, v0.w, acc.w);     \
        }                                                                     \
    }                                                                         \
    acc.x += __shfl_xor_sync(FULLMASK, acc.x, 16);                            \
    acc.y += __shfl_xor_sync(FULLMASK, acc.y, 16);                            \
    acc.z += __shfl_xor_sync(FULLMASK, acc.z, 16);                            \
    acc.w += __shfl_xor_sync(FULLMASK, acc.w, 16);                            \
    if (half == 0) {                                                          \
        float4 bb = __ldg((const float4*)(BIASP) + l4);                       \
        acc.x = fmaxf(acc.x + bb.x, 0.f);                                     \
        acc.y = fmaxf(acc.y + bb.y, 0.f);                                     \
        acc.z = fmaxf(acc.z + bb.z, 0.f);                                     \
        acc.w = fmaxf(acc.w + bb.w, 0.f);                                     \
        ((float4*)Row[warp])[l4] = acc;                                       \
    }                                                                         \
    __syncwarp();

    // ---- P7: t2 = relu(agg(t1)+b1) @ W2  (g_P -> g_Q, 64-wide) -------------
    {
        float (*Row)[64] = (float(*)[64])(smem_raw + 16384);
        for (int i = tid; i < 4096; i += 256) Ws[i] = W2[i];
        __syncthreads();
        for (int nf = gwarp; nf < NN2; nf += NWARP_TOT) {
            int gi = nf >= NN;
            int n  = nf - gi * NN;
            AGG64_BODY(g_P, b1)
            const float* r = Row[warp];
            float2 o = make_float2(0.f, 0.f);
#pragma unroll
            for (int k = 0; k < 64; k++) {
                float xk = r[k];
                float2 wv = ((const float2*)(Ws + k * 64))[lane];
                o.x = fmaf(xk, wv.x, o.x);
                o.y = fmaf(xk, wv.y, o.y);
            }
            ((float2*)(g_Q + gi * NN * 64 + n * 64))[lane] = o;
            __syncwarp();
        }
    }
    gridsync();

    // ---- P8: t3 = relu(agg(t2)+b2) @ W3  (g_Q -> g_P, 32-wide rows) --------
    {
        float (*Row)[64] = (float(*)[64])(smem_raw + 16384);
        for (int i = tid; i < 2048; i += 256) Ws[i] = W3[i];
        __syncthreads();
        for (int nf = gwarp; nf < NN2; nf += NWARP_TOT) {
            int gi = nf >= NN;
            int n  = nf - gi * NN;
            AGG64_BODY(g_Q, b2)
            const float* r = Row[warp];
            float o = 0.f;
#pragma unroll
            for (int k = 0; k < 64; k++)
                o = fmaf(r[k], Ws[k * 32 + lane], o);
            g_P[gi * NN * 64 + n * 32 + lane] = o;
            __syncwarp();
        }
    }
    gridsync();

    // ---- P9: a3 = agg(t3)+b3 (g_P -> g_Q, 32-wide) + fused column sums -----
    {
        float* part = (float*)(smem_raw + 16384);          // [2][32]
        if (tid < 64) part[tid] = 0.f;
        __syncthreads();
        float2 bb = __ldg((const float2*)b3 + l4);
        float2 cs0 = make_float2(0.f, 0.f), cs1 = make_float2(0.f, 0.f);
        for (int nf = gwarp; nf < NN2; nf += NWARP_TOT) {
            int gi = nf >= NN;
            int n  = nf - gi * NN;
            const float* H = g_P + gi * NN * 64;           // 32-wide rows
            const int2* eb = g_csr + g_rowptr[nf];
            int cnt  = g_deg[nf];
            float dv = g_dinv[nf];
            float2 acc;
            if (half == 0) {
                float2 v = __ldg((const float2*)(H + n * 32) + l4);
                float d2 = dv * dv;
                acc.x = v.x * d2; acc.y = v.y * d2;
            } else acc = make_float2(0.f, 0.f);
            int base = 0;
            for (; base + 8 <= cnt; base += 8) {
                int2 r0 = __ldg(eb + base     + half);
                int2 r1 = __ldg(eb + base + 2 + half);
                int2 r2 = __ldg(eb + base + 4 + half);
                int2 r3 = __ldg(eb + base + 6 + half);
                float2 v0 = __ldg((const float2*)(H + r0.x * 32) + l4);
                float2 v1 = __ldg((const float2*)(H + r1.x * 32) + l4);
                float2 v2 = __ldg((const float2*)(H + r2.x * 32) + l4);
                float2 v3 = __ldg((const float2*)(H + r3.x * 32) + l4);
                acc.x = fmaf(__int_as_float(r0.y), v0.x, acc.x);
                acc.y = fmaf(__int_as_float(r0.y), v0.y, acc.y);
                acc.x = fmaf(__int_as_float(r1.y), v1.x, acc.x);
                acc.y = fmaf(__int_as_float(r1.y), v1.y, acc.y);
                acc.x = fmaf(__int_as_float(r2.y), v2.x, acc.x);
                acc.y = fmaf(__int_as_float(r2.y), v2.y, acc.y);
                acc.x = fmaf(__int_as_float(r3.y), v3.x, acc.x);
                acc.y = fmaf(__int_as_float(r3.y), v3.y, acc.y);
            }
            for (; base < cnt; base += 2) {
                int idx = base + half;
                if (idx < cnt) {
                    int2 r0 = __ldg(eb + idx);
                    float2 v0 = __ldg((const float2*)(H + r0.x * 32) + l4);
                    acc.x = fmaf(__int_as_float(r0.y), v0.x, acc.x);
                    acc.y = fmaf(__int_as_float(r0.y), v0.y, acc.y);
                }
            }
            acc.x += __shfl_xor_sync(FULLMASK, acc.x, 16);
            acc.y += __shfl_xor_sync(FULLMASK, acc.y, 16);
            if (half == 0) {
                acc.x += bb.x;
                acc.y += bb.y;
                ((float2*)(g_Q + gi * NN * 64 + n * 32))[l4] = acc;
                if (gi) { cs1.x += acc.x; cs1.y += acc.y; }
                else    { cs0.x += acc.x; cs0.y += acc.y; }
            }
            __syncwarp();
        }
        if (half == 0) {
            atomicAdd(&part[2 * l4],          cs0.x);
            atomicAdd(&part[2 * l4 + 1],      cs0.y);
            atomicAdd(&part[32 + 2 * l4],     cs1.x);
            atomicAdd(&part[32 + 2 * l4 + 1], cs1.y);
        }
        __syncthreads();
        if (tid < 64) atomicAdd(&((float*)g_m)[tid], part[tid]);
    }
    gridsync();

    // ---- P11: attention pool (ctx computed per block; warp-per-row) --------
    {
        float* ctxs = (float*)(smem_raw + 16384);          // [2][32]
        float* part = (float*)(smem_raw + 16640);          // [2][32]
        if (warp == 0) {
            float a0 = 0.f, a1 = 0.f;
#pragma unroll
            for (int k = 0; k < F3; k++) {
                float w = __ldg(&Watt[k * F3 + lane]);
                a0 += g_m[0][k] * w;
                a1 += g_m[1][k] * w;
            }
            ctxs[lane]      = tanhf(a0 * (1.0f / NN));
            ctxs[32 + lane] = tanhf(a1 * (1.0f / NN));
        }
        if (tid < 64) part[tid] = 0.f;
        __syncthreads();
        float c0 = ctxs[lane], c1 = ctxs[32 + lane];
        float a0 = 0.f, a1 = 0.f;
        for (int nf = gwarp; nf < NN2; nf += NWARP_TOT) {
            int gi = nf >= NN;
            int n  = nf - gi * NN;
            float v = __ldg(g_Q + gi * NN * 64 + n * 32 + lane);
            float p = v * (gi ? c1 : c0);
#pragma unroll
            for (int o = 16; o >= 1; o >>= 1)
                p += __shfl_xor_sync(FULLMASK, p, o);
            float s = 1.f / (1.f + expf(-p));
            if (gi) a1 = fmaf(v, s, a1); else a0 = fmaf(v, s, a0);
        }
        atomicAdd(&part[lane],      a0);
        atomicAdd(&part[32 + lane], a1);
        __syncthreads();
        if (tid < 64) atomicAdd(&((float*)g_pool)[tid], part[tid]);
    }
    gridsync();

    // ---- P12: NTN scoring (block 0) ----------------------------------------
    if (bid == 0) {
        float* e12 = (float*)smem_raw;                     // 64 floats
        float* red = (float*)(smem_raw + 256);             // 256 floats
        if (tid < 64) e12[tid] = ((float*)g_pool)[tid];
        __syncthreads();
        int k = tid & 15, ih = tid >> 4;                   // ih: 0..15
        float s = 0.f;
#pragma unroll
        for (int halfq = 0; halfq < 2; halfq++) {
            int i = ih + halfq * 16;
            float a = e12[i];
            for (int j = 0; j < F3; j++)
                s = fmaf(a * e12[32 + j], __ldg(&Wtn[(i * F3 + j) * KK + k]), s);
        }
        red[tid] = s;
        __syncthreads();
#pragma unroll
        for (int off = 128; off >= 16; off >>= 1) {
            if (tid < off) red[tid] += red[tid + off];
            __syncthreads();
        }
        if (tid < KK) {
            float bl = 0.f;
#pragma unroll
            for (int i = 0; i < 64; i++)
                bl += Wb[tid * 64 + i] * e12[i];
            float v = red[tid] + bl + btn[tid];
            out[tid] = v > 0.f ? v : 0.f;
        }
    }
}

// ---------------- driver ----------------------------------------------------
extern "C" void kernel_launch(void* const* d_in, const int* in_sizes, int n_in,
                              void* d_out, int out_size) {
    mega_kernel<<<NBLK, NTHREAD>>>(
        (const float*)d_in[0], (const int*)d_in[1],
        (const float*)d_in[2], (const int*)d_in[3],
        (const float*)d_in[4], (const float*)d_in[5],
        (const float*)d_in[6], (const float*)d_in[7],
        (const float*)d_in[8], (const float*)d_in[9],
        (const float*)d_in[10],
        (const float*)d_in[11], (const float*)d_in[12],
        (const float*)d_in[13], (float*)d_out);
}

// round 17
// speedup vs baseline: 20.4940x; 1.1360x over previous
#include <cuda_runtime.h>
#include <math.h>

// Problem constants (fixed by the reference)
#define NN   50000
#define EE   800000
#define F3   32
#define KK   16
#define NN2  (2*NN)                    // 100000 nodes total
#define EE2  (2*EE)                    // 1.6M edges total
#define NBLK 592                       // 148 SMs * 4 blocks (guaranteed resident)
#define NTHREAD 256
#define NTH_TOT (NBLK*NTHREAD)
#define NWARP_TOT (NBLK*8)
#define NCHUNK ((NN2+255)/256)         // 391 scan chunks
#define FULLMASK 0xffffffffu

// ---------------- scratch (__device__ globals; no allocs allowed) ----------
__device__ float g_P[NN2*64];          // activations ping (per-graph halves)
__device__ float g_Q[NN2*64];          // activations pong
__device__ int2  g_csr[EE2];           // flat CSR records {src_local, bits(w)}
__device__ int   g_rowptr[NN2];        // global flat row offsets into g_csr
__device__ int   g_deg[NN2];
__device__ int   g_cur[NN2];
__device__ int   g_scanTmp[NN2];
__device__ int   g_bsum[NCHUNK];
__device__ int   g_boff[NCHUNK];
__device__ float g_dinv[NN2];
__device__ float g_m[2][F3];
__device__ float g_pool[2][F3];
__device__ unsigned g_bar_cnt = 0;
__device__ unsigned g_bar_gen = 0;

// ---------------- software grid barrier (all NBLK blocks resident) ---------
__device__ __forceinline__ void gridsync() {
    __syncthreads();
    if (threadIdx.x == 0) {
        __threadfence();
        unsigned gen = *(volatile unsigned*)&g_bar_gen;
        if (atomicAdd(&g_bar_cnt, 1u) == NBLK - 1) {
            atomicExch(&g_bar_cnt, 0u);
            __threadfence();
            *(volatile unsigned*)&g_bar_gen = gen + 1u;
        } else {
            while (*(volatile unsigned*)&g_bar_gen == gen) { }
        }
        __threadfence();
    }
    __syncthreads();
}

// ---------------- the whole SimGNN forward in one kernel --------------------
__global__ void __launch_bounds__(NTHREAD, 4) mega_kernel(
    const float* __restrict__ f0, const int* __restrict__ e0,
    const float* __restrict__ f1, const int* __restrict__ e1,
    const float* __restrict__ W1, const float* __restrict__ b1,
    const float* __restrict__ W2, const float* __restrict__ b2,
    const float* __restrict__ W3, const float* __restrict__ b3,
    const float* __restrict__ Watt,
    const float* __restrict__ Wtn, const float* __restrict__ Wb,
    const float* __restrict__ btn, float* __restrict__ out)
{
    // 16 KB weights + 8 warps * 4 rows * 68 floats (epilogue row batch)
    __shared__ __align__(16) char smem_raw[16384 + 8*4*68*4];
    float* Ws = (float*)smem_raw;

    const int tid   = threadIdx.x;
    const int bid   = blockIdx.x;
    const int gtid  = bid * NTHREAD + tid;
    const int warp  = tid >> 5, lane = tid & 31;
    const int gwarp = bid * 8 + warp;
    const int half  = lane >> 4;       // dual-edge half id
    const int l4    = lane & 15;       // column group within half

    const int*   edge[2] = { e0, e1 };
    const float* feat[2] = { f0, f1 };

    // ---- P0: init ----------------------------------------------------------
    for (int i = gtid; i < NN2; i += NTH_TOT) { g_deg[i] = 0; g_cur[i] = 0; }
    if (gtid < 64) { ((float*)g_m)[gtid] = 0.f; ((float*)g_pool)[gtid] = 0.f; }
    gridsync();

    // ---- P1: degree count (int4-vectorized) --------------------------------
    for (int e4 = gtid; e4 < EE2 / 4; e4 += NTH_TOT) {
        int gi = e4 >= EE / 4;
        int l  = e4 - gi * (EE / 4);
        int4 d = __ldg((const int4*)(edge[gi] + EE) + l);
        int* dg = g_deg + gi * NN;
        atomicAdd(dg + d.x, 1); atomicAdd(dg + d.y, 1);
        atomicAdd(dg + d.z, 1); atomicAdd(dg + d.w, 1);
    }
    gridsync();

    // ---- P2: per-chunk inclusive scan (256 elems/chunk) --------------------
    {
        int* sh = (int*)smem_raw;
        for (int c = bid; c < NCHUNK; c += NBLK) {
            int i = c * 256 + tid;
            int v = (i < NN2) ? g_deg[i] : 0;
            sh[tid] = v;
            __syncthreads();
#pragma unroll
            for (int off = 1; off < 256; off <<= 1) {
                int x = (tid >= off) ? sh[tid - off] : 0;
                __syncthreads();
                sh[tid] += x;
                __syncthreads();
            }
            if (i < NN2) g_scanTmp[i] = sh[tid];
            if (tid == 255) g_bsum[c] = sh[255];
            __syncthreads();
        }
    }
    gridsync();

    // ---- P3: scan chunk totals (block 0, warp 0, serial-carry) -------------
    if (bid == 0 && warp == 0) {
        int carry = 0;
        for (int base = 0; base < NCHUNK; base += 32) {
            int idx = base + lane;
            int v = (idx < NCHUNK) ? g_bsum[idx] : 0;
            int orig = v;
#pragma unroll
            for (int o = 1; o < 32; o <<= 1) {
                int t2 = __shfl_up_sync(FULLMASK, v, o);
                if (lane >= o) v += t2;
            }
            if (idx < NCHUNK) g_boff[idx] = carry + v - orig;   // exclusive
            carry += __shfl_sync(FULLMASK, v, 31);
        }
    }
    gridsync();

    // ---- P4: rowptr + dinv -------------------------------------------------
    for (int i = gtid; i < NN2; i += NTH_TOT) {
        int d = g_deg[i];
        g_rowptr[i] = g_scanTmp[i] - d + g_boff[i >> 8];
        g_dinv[i]   = rsqrtf((float)(d + 1));        // +1 self loop
    }
    gridsync();

    // ---- P5: CSR placement (int4-vectorized loads) -------------------------
    for (int e4 = gtid; e4 < EE2 / 4; e4 += NTH_TOT) {
        int gi = e4 >= EE / 4;
        int l  = e4 - gi * (EE / 4);
        int4 s4 = __ldg((const int4*)(edge[gi]) + l);
        int4 d4 = __ldg((const int4*)(edge[gi] + EE) + l);
        const float* dv = g_dinv + gi * NN;
        int base = gi * NN;
#pragma unroll
        for (int u = 0; u < 4; u++) {
            int s = (u == 0) ? s4.x : (u == 1) ? s4.y : (u == 2) ? s4.z : s4.w;
            int d = (u == 0) ? d4.x : (u == 1) ? d4.y : (u == 2) ? d4.z : d4.w;
            int gd = base + d;
            int pos = g_rowptr[gd] + atomicAdd(&g_cur[gd], 1);
            int2 rec;
            rec.x = s;
            rec.y = __float_as_int(dv[s] * g_dinv[gd]);
            g_csr[pos] = rec;
        }
    }
    gridsync();

    // ---- P6: layer-1 gemm  t1 = X @ W1  -> g_P (64-wide) -------------------
    {
        float (*Xs)[65] = (float(*)[65])(smem_raw + 16384);
        for (int i = tid; i < 4096; i += 256) Ws[i] = W1[i];
        __syncthreads();
        int tx = tid & 15, ty = tid >> 4;
        for (int tt = bid; tt < 6250; tt += NBLK) {       // 2 * 3125 row tiles
            int gi = tt >= 3125;
            int r0 = (tt - gi * 3125) * 16;
            const float* X = feat[gi];
            for (int i = tid; i < 16 * 64; i += 256) {
                int r = i >> 6, c = i & 63;
                Xs[r][c] = (r0 + r < NN) ? X[(r0 + r) * 64 + c] : 0.f;
            }
            __syncthreads();
            int row = r0 + ty;
            if (row < NN) {
                float4 acc = make_float4(0.f, 0.f, 0.f, 0.f);
                const float4* Ws4 = (const float4*)Ws;
#pragma unroll
                for (int k = 0; k < 64; k++) {
                    float xv = Xs[ty][k];
                    float4 wv = Ws4[k * 16 + tx];
                    acc.x = fmaf(xv, wv.x, acc.x);
                    acc.y = fmaf(xv, wv.y, acc.y);
                    acc.z = fmaf(xv, wv.z, acc.z);
                    acc.w = fmaf(xv, wv.w, acc.w);
                }
                ((float4*)(g_P + (gi * NN + row) * 64))[tx] = acc;
            }
            __syncthreads();
        }
    }
    gridsync();

    // ==== P7 / P8: fused agg + batched-epilogue gemm layers =================
    // Dual-edge half-warp agg; 4 nodes aggregated per warp into smem rows,
    // then ONE 4-row epilogue so each Ws read is amortized 4x.
#define AGG64_BODY(SRC, BIASP, RIDX)                                          \
    const float* H = SRC + gi * NN * 64;                                      \
    const int2* eb = g_csr + g_rowptr[nf];                                    \
    int cnt  = g_deg[nf];                                                     \
    float dv = g_dinv[nf];                                                    \
    float4 acc;                                                               \
    if (half == 0) {                                                          \
        float4 v = __ldg((const float4*)(H + n * 64) + l4);                   \
        float d2 = dv * dv;                                                   \
        acc.x = v.x * d2; acc.y = v.y * d2; acc.z = v.z * d2; acc.w = v.w * d2;\
    } else acc = make_float4(0.f, 0.f, 0.f, 0.f);                             \
    int base = 0;                                                             \
    for (; base + 8 <= cnt; base += 8) {                                      \
        int2 r0 = __ldg(eb + base     + half);                                \
        int2 r1 = __ldg(eb + base + 2 + half);                                \
        int2 r2 = __ldg(eb + base + 4 + half);                                \
        int2 r3 = __ldg(eb + base + 6 + half);                                \
        float4 v0 = __ldg((const float4*)(H + r0.x * 64) + l4);               \
        float4 v1 = __ldg((const float4*)(H + r1.x * 64) + l4);               \
        float4 v2 = __ldg((const float4*)(H + r2.x * 64) + l4);               \
        float4 v3 = __ldg((const float4*)(H + r3.x * 64) + l4);               \
        float w0 = __int_as_float(r0.y), w1 = __int_as_float(r1.y);           \
        float w2 = __int_as_float(r2.y), w3 = __int_as_float(r3.y);           \
        acc.x = fmaf(w0, v0.x, acc.x); acc.y = fmaf(w0, v0.y, acc.y);         \
        acc.z = fmaf(w0, v0.z, acc.z); acc.w = fmaf(w0, v0.w, acc.w);         \
        acc.x = fmaf(w1, v1.x, acc.x); acc.y = fmaf(w1, v1.y, acc.y);         \
        acc.z = fmaf(w1, v1.z, acc.z); acc.w = fmaf(w1, v1.w, acc.w);         \
        acc.x = fmaf(w2, v2.x, acc.x); acc.y = fmaf(w2, v2.y, acc.y);         \
        acc.z = fmaf(w2, v2.z, acc.z); acc.w = fmaf(w2, v2.w, acc.w);         \
        acc.x = fmaf(w3, v3.x, acc.x); acc.y = fmaf(w3, v3.y, acc.y);         \
        acc.z = fmaf(w3, v3.z, acc.z); acc.w = fmaf(w3, v3.w, acc.w);         \
    }                                                                         \
    for (; base < cnt; base += 2) {                                           \
        int idx = base + half;                                                \
        if (idx < cnt) {                                                      \
            int2 r0 = __ldg(eb + idx);                                        \
            float4 v0 = __ldg((const float4*)(H + r0.x * 64) + l4);           \
            float w0 = __int_as_float(r0.y);                                  \
            acc.x = fmaf(w0, v0.x, acc.x); acc.y = fmaf(w0, v0.y, acc.y);     \
            acc.z = fmaf(w0, v0.z, acc.z); acc.w = fmaf(w0, v0.w, acc.w);     \
        }                                                                     \
    }                                                                         \
    acc.x += __shfl_xor_sync(FULLMASK, acc.x, 16);                            \
    acc.y += __shfl_xor_sync(FULLMASK, acc.y, 16);                            \
    acc.z += __shfl_xor_sync(FULLMASK, acc.z, 16);                            \
    acc.w += __shfl_xor_sync(FULLMASK, acc.w, 16);                            \
    if (half == 0) {                                                          \
        float4 bb = __ldg((const float4*)(BIASP) + l4);                       \
        acc.x = fmaxf(acc.x + bb.x, 0.f);                                     \
        acc.y = fmaxf(acc.y + bb.y, 0.f);                                     \
        acc.z = fmaxf(acc.z + bb.z, 0.f);                                     \
        acc.w = fmaxf(acc.w + bb.w, 0.f);                                     \
        ((float4*)Row[warp][RIDX])[l4] = acc;                                 \
    }                                                                         \
    __syncwarp();

    // ---- P7: t2 = relu(agg(t1)+b1) @ W2  (g_P -> g_Q, 64-wide) -------------
    {
        float (*Row)[4][68] = (float(*)[4][68])(smem_raw + 16384);
        for (int i = tid; i < 4096; i += 256) Ws[i] = W2[i];
        __syncthreads();
        for (int g0 = gwarp * 4; g0 < NN2; g0 += NWARP_TOT * 4) {
#pragma unroll 1
            for (int r = 0; r < 4; r++) {
                int nf = g0 + r;
                int gi = nf >= NN;
                int n  = nf - gi * NN;
                AGG64_BODY(g_P, b1, r)
            }
            // batched 4-row epilogue: o[r] = Row[r] @ W2
            const float* R0 = Row[warp][0];
            const float* R1 = Row[warp][1];
            const float* R2 = Row[warp][2];
            const float* R3 = Row[warp][3];
            float2 o0 = make_float2(0.f, 0.f), o1 = o0, o2 = o0, o3 = o0;
#pragma unroll
            for (int k = 0; k < 64; k++) {
                float2 wv = ((const float2*)(Ws + k * 64))[lane];
                float x0 = R0[k], x1 = R1[k], x2 = R2[k], x3 = R3[k];
                o0.x = fmaf(x0, wv.x, o0.x); o0.y = fmaf(x0, wv.y, o0.y);
                o1.x = fmaf(x1, wv.x, o1.x); o1.y = fmaf(x1, wv.y, o1.y);
                o2.x = fmaf(x2, wv.x, o2.x); o2.y = fmaf(x2, wv.y, o2.y);
                o3.x = fmaf(x3, wv.x, o3.x); o3.y = fmaf(x3, wv.y, o3.y);
            }
#pragma unroll
            for (int r = 0; r < 4; r++) {
                int nf = g0 + r;
                int gi = nf >= NN;
                int n  = nf - gi * NN;
                float2 o = (r == 0) ? o0 : (r == 1) ? o1 : (r == 2) ? o2 : o3;
                ((float2*)(g_Q + gi * NN * 64 + n * 64))[lane] = o;
            }
            __syncwarp();
        }
    }
    gridsync();

    // ---- P8: t3 = relu(agg(t2)+b2) @ W3  (g_Q -> g_P, 32-wide rows) --------
    {
        float (*Row)[4][68] = (float(*)[4][68])(smem_raw + 16384);
        for (int i = tid; i < 2048; i += 256) Ws[i] = W3[i];
        __syncthreads();
        for (int g0 = gwarp * 4; g0 < NN2; g0 += NWARP_TOT * 4) {
#pragma unroll 1
            for (int r = 0; r < 4; r++) {
                int nf = g0 + r;
                int gi = nf >= NN;
                int n  = nf - gi * NN;
                AGG64_BODY(g_Q, b2, r)
            }
            const float* R0 = Row[warp][0];
            const float* R1 = Row[warp][1];
            const float* R2 = Row[warp][2];
            const float* R3 = Row[warp][3];
            float o0 = 0.f, o1 = 0.f, o2 = 0.f, o3 = 0.f;
#pragma unroll
            for (int k = 0; k < 64; k++) {
                float wv = Ws[k * 32 + lane];
                o0 = fmaf(R0[k], wv, o0);
                o1 = fmaf(R1[k], wv, o1);
                o2 = fmaf(R2[k], wv, o2);
                o3 = fmaf(R3[k], wv, o3);
            }
#pragma unroll
            for (int r = 0; r < 4; r++) {
                int nf = g0 + r;
                int gi = nf >= NN;
                int n  = nf - gi * NN;
                float o = (r == 0) ? o0 : (r == 1) ? o1 : (r == 2) ? o2 : o3;
                g_P[gi * NN * 64 + n * 32 + lane] = o;
            }
            __syncwarp();
        }
    }
    gridsync();

    // ---- P9: a3 = agg(t3)+b3 (g_P -> g_Q, 32-wide) + fused column sums -----
    {
        float* part = (float*)(smem_raw + 16384);          // [2][32]
        if (tid < 64) part[tid] = 0.f;
        __syncthreads();
        float2 bb = __ldg((const float2*)b3 + l4);
        float2 cs0 = make_float2(0.f, 0.f), cs1 = make_float2(0.f, 0.f);
        for (int nf = gwarp; nf < NN2; nf += NWARP_TOT) {
            int gi = nf >= NN;
            int n  = nf - gi * NN;
            const float* H = g_P + gi * NN * 64;           // 32-wide rows
            const int2* eb = g_csr + g_rowptr[nf];
            int cnt  = g_deg[nf];
            float dv = g_dinv[nf];
            float2 acc;
            if (half == 0) {
                float2 v = __ldg((const float2*)(H + n * 32) + l4);
                float d2 = dv * dv;
                acc.x = v.x * d2; acc.y = v.y * d2;
            } else acc = make_float2(0.f, 0.f);
            int base = 0;
            for (; base + 8 <= cnt; base += 8) {
                int2 r0 = __ldg(eb + base     + half);
                int2 r1 = __ldg(eb + base + 2 + half);
                int2 r2 = __ldg(eb + base + 4 + half);
                int2 r3 = __ldg(eb + base + 6 + half);
                float2 v0 = __ldg((const float2*)(H + r0.x * 32) + l4);
                float2 v1 = __ldg((const float2*)(H + r1.x * 32) + l4);
                float2 v2 = __ldg((const float2*)(H + r2.x * 32) + l4);
                float2 v3 = __ldg((const float2*)(H + r3.x * 32) + l4);
                acc.x = fmaf(__int_as_float(r0.y), v0.x, acc.x);
                acc.y = fmaf(__int_as_float(r0.y), v0.y, acc.y);
                acc.x = fmaf(__int_as_float(r1.y), v1.x, acc.x);
                acc.y = fmaf(__int_as_float(r1.y), v1.y, acc.y);
                acc.x = fmaf(__int_as_float(r2.y), v2.x, acc.x);
                acc.y = fmaf(__int_as_float(r2.y), v2.y, acc.y);
                acc.x = fmaf(__int_as_float(r3.y), v3.x, acc.x);
                acc.y = fmaf(__int_as_float(r3.y), v3.y, acc.y);
            }
            for (; base < cnt; base += 2) {
                int idx = base + half;
                if (idx < cnt) {
                    int2 r0 = __ldg(eb + idx);
                    float2 v0 = __ldg((const float2*)(H + r0.x * 32) + l4);
                    acc.x = fmaf(__int_as_float(r0.y), v0.x, acc.x);
                    acc.y = fmaf(__int_as_float(r0.y), v0.y, acc.y);
                }
            }
            acc.x += __shfl_xor_sync(FULLMASK, acc.x, 16);
            acc.y += __shfl_xor_sync(FULLMASK, acc.y, 16);
            if (half == 0) {
                acc.x += bb.x;
                acc.y += bb.y;
                ((float2*)(g_Q + gi * NN * 64 + n * 32))[l4] = acc;
                if (gi) { cs1.x += acc.x; cs1.y += acc.y; }
                else    { cs0.x += acc.x; cs0.y += acc.y; }
            }
            __syncwarp();
        }
        if (half == 0) {
            atomicAdd(&part[2 * l4],          cs0.x);
            atomicAdd(&part[2 * l4 + 1],      cs0.y);
            atomicAdd(&part[32 + 2 * l4],     cs1.x);
            atomicAdd(&part[32 + 2 * l4 + 1], cs1.y);
        }
        __syncthreads();
        if (tid < 64) atomicAdd(&((float*)g_m)[tid], part[tid]);
    }
    gridsync();

    // ---- P11: attention pool (ctx computed per block; warp-per-row) --------
    {
        float* ctxs = (float*)(smem_raw + 16384);          // [2][32]
        float* part = (float*)(smem_raw + 16640);          // [2][32]
        if (warp == 0) {
            float a0 = 0.f, a1 = 0.f;
#pragma unroll
            for (int k = 0; k < F3; k++) {
                float w = __ldg(&Watt[k * F3 + lane]);
                a0 += g_m[0][k] * w;
                a1 += g_m[1][k] * w;
            }
            ctxs[lane]      = tanhf(a0 * (1.0f / NN));
            ctxs[32 + lane] = tanhf(a1 * (1.0f / NN));
        }
        if (tid < 64) part[tid] = 0.f;
        __syncthreads();
        float c0 = ctxs[lane], c1 = ctxs[32 + lane];
        float a0 = 0.f, a1 = 0.f;
        for (int nf = gwarp; nf < NN2; nf += NWARP_TOT) {
            int gi = nf >= NN;
            int n  = nf - gi * NN;
            float v = __ldg(g_Q + gi * NN * 64 + n * 32 + lane);
            float p = v * (gi ? c1 : c0);
#pragma unroll
            for (int o = 16; o >= 1; o >>= 1)
                p += __shfl_xor_sync(FULLMASK, p, o);
            float s = 1.f / (1.f + expf(-p));
            if (gi) a1 = fmaf(v, s, a1); else a0 = fmaf(v, s, a0);
        }
        atomicAdd(&part[lane],      a0);
        atomicAdd(&part[32 + lane], a1);
        __syncthreads();
        if (tid < 64) atomicAdd(&((float*)g_pool)[tid], part[tid]);
    }
    gridsync();

    // ---- P12: NTN scoring (block 0) ----------------------------------------
    if (bid == 0) {
        float* e12 = (float*)smem_raw;                     // 64 floats
        float* red = (float*)(smem_raw + 256);             // 256 floats
        if (tid < 64) e12[tid] = ((float*)g_pool)[tid];
        __syncthreads();
        int k = tid & 15, ih = tid >> 4;                   // ih: 0..15
        float s = 0.f;
#pragma unroll
        for (int halfq = 0; halfq < 2; halfq++) {
            int i = ih + halfq * 16;
            float a = e12[i];
            for (int j = 0; j < F3; j++)
                s = fmaf(a * e12[32 + j], __ldg(&Wtn[(i * F3 + j) * KK + k]), s);
        }
        red[tid] = s;
        __syncthreads();
#pragma unroll
        for (int off = 128; off >= 16; off >>= 1) {
            if (tid < off) red[tid] += red[tid + off];
            __syncthreads();
        }
        if (tid < KK) {
            float bl = 0.f;
#pragma unroll
            for (int i = 0; i < 64; i++)
                bl += Wb[tid * 64 + i] * e12[i];
            float v = red[tid] + bl + btn[tid];
            out[tid] = v > 0.f ? v : 0.f;
        }
    }
}

// ---------------- driver ----------------------------------------------------
extern "C" void kernel_launch(void* const* d_in, const int* in_sizes, int n_in,
                              void* d_out, int out_size) {
    mega_kernel<<<NBLK, NTHREAD>>>(
        (const float*)d_in[0], (const int*)d_in[1],
        (const float*)d_in[2], (const int*)d_in[3],
        (const float*)d_in[4], (const float*)d_in[5],
        (const float*)d_in[6], (const float*)d_in[7],
        (const float*)d_in[8], (const float*)d_in[9],
        (const float*)d_in[10],
        (const float*)d_in[11], (const float*)d_in[12],
        (const float*)d_in[13], (float*)d_out);
}